// round 3
// baseline (speedup 1.0000x reference)
#include <cuda_runtime.h>
#include <math.h>

// ExponentialUnitNorm: y = x / sqrt(s_t), s_t = 0.01*|x_t| + 0.99*s_{t-1}
// Shapes: x [B=16, C=1, T=2000, F=481, 2] f32, init_state [1,1,F,1] f32.
//
// Exact chunked linear-recurrence scan:
//   pass 1: per (b, chunk, f) compute chunk partial P (recurrence from 0)
//   pass 2: per (b, f) chain incoming states: s_in[c+1] = a^L * s_in[c] + P[c]
//   pass 3: per (b, chunk, f) replay recurrence from s_in, write y
// Parallelism: B*NC*F = 192,400 threads for passes 1/3 (vs 7,696 serial chains).

namespace {
constexpr int B  = 16;
constexpr int T  = 2000;
constexpr int Fq = 481;
constexpr int NC = 25;          // chunks over T
constexpr int L  = T / NC;      // 80
constexpr float AL  = 0.99f;
constexpr float OMA = 0.01f;    // 1 - alpha
constexpr float EPSC = 1e-14f;
constexpr int UN = 8;           // unroll / prefetch depth
}

__device__ float g_P[B * NC * Fq];   // chunk partials
__device__ float g_S[B * NC * Fq];   // incoming state per chunk

__global__ __launch_bounds__(512) void k_partial(const float* __restrict__ x) {
    const int f = threadIdx.x;
    if (f >= Fq) return;
    const int c = blockIdx.x;
    const int b = blockIdx.y;
    const float2* xp = reinterpret_cast<const float2*>(x)
                       + (size_t)(b * T + c * L) * Fq + f;
    float p = 0.0f;
    #pragma unroll 1
    for (int i = 0; i < L; i += UN) {
        float2 v[UN];
        #pragma unroll
        for (int j = 0; j < UN; ++j) v[j] = xp[(size_t)(i + j) * Fq];
        #pragma unroll
        for (int j = 0; j < UN; ++j) {
            float r2  = fmaxf(fmaf(v[j].x, v[j].x, v[j].y * v[j].y), EPSC);
            float mag = r2 * rsqrtf(r2);
            p = fmaf(mag, OMA, p * AL);
        }
    }
    g_P[((size_t)b * NC + c) * Fq + f] = p;
}

__global__ void k_combine(const float* __restrict__ init_state, float aL) {
    const int idx = blockIdx.x * blockDim.x + threadIdx.x;
    if (idx >= B * Fq) return;
    const int b = idx / Fq;
    const int f = idx - b * Fq;
    float s = init_state[f];
    #pragma unroll
    for (int c = 0; c < NC; ++c) {
        const size_t o = ((size_t)b * NC + c) * Fq + f;
        g_S[o] = s;
        s = fmaf(aL, s, g_P[o]);
    }
}

__global__ __launch_bounds__(512) void k_apply(const float* __restrict__ x,
                                               float* __restrict__ y) {
    const int f = threadIdx.x;
    if (f >= Fq) return;
    const int c = blockIdx.x;
    const int b = blockIdx.y;
    const size_t base = (size_t)(b * T + c * L) * Fq + f;
    const float2* xp = reinterpret_cast<const float2*>(x) + base;
    float2*       yp = reinterpret_cast<float2*>(y) + base;
    float s = g_S[((size_t)b * NC + c) * Fq + f];
    #pragma unroll 1
    for (int i = 0; i < L; i += UN) {
        float2 v[UN];
        #pragma unroll
        for (int j = 0; j < UN; ++j) v[j] = xp[(size_t)(i + j) * Fq];
        #pragma unroll
        for (int j = 0; j < UN; ++j) {
            float r2  = fmaxf(fmaf(v[j].x, v[j].x, v[j].y * v[j].y), EPSC);
            float mag = r2 * rsqrtf(r2);
            s = fmaf(mag, OMA, s * AL);
            float sc = rsqrtf(s);
            v[j].x *= sc;
            v[j].y *= sc;
        }
        #pragma unroll
        for (int j = 0; j < UN; ++j) yp[(size_t)(i + j) * Fq] = v[j];
    }
}

extern "C" void kernel_launch(void* const* d_in, const int* in_sizes, int n_in,
                              void* d_out, int out_size) {
    // metadata order: x (B*T*F*2 elems), init_state (F elems). Be defensive.
    const float* x    = (const float*)d_in[0];
    const float* init = (const float*)d_in[1];
    if (n_in >= 2 && in_sizes[0] == Fq) {  // swapped order
        x    = (const float*)d_in[1];
        init = (const float*)d_in[0];
    }
    float* y = (float*)d_out;

    const float aL = (float)pow((double)AL, (double)L);  // alpha^L

    dim3 grid(NC, B);
    k_partial<<<grid, 512>>>(x);
    k_combine<<<(B * Fq + 255) / 256, 256>>>(init, aL);
    k_apply<<<grid, 512>>>(x, y);
}